// round 1
// baseline (speedup 1.0000x reference)
#include <cuda_runtime.h>
#include <math.h>

// Problem constants (shape-stable per registry)
#define DID 4096      // hidden dim
#define EXP 64        // experts
// K (top-k) = 2

typedef unsigned long long u64;

__device__ float g_importance[EXP];
__device__ int   g_load[EXP];

__global__ void init_kernel() {
    int t = threadIdx.x;
    if (t < EXP) { g_importance[t] = 0.0f; g_load[t] = 0; }
}

__device__ __forceinline__ u64 dup2f(float a) {
    u64 r; asm("mov.b64 %0, {%1, %1};" : "=l"(r) : "f"(a)); return r;
}
__device__ __forceinline__ void ffma2(u64& d, u64 a, u64 b) {
    asm("fma.rn.f32x2 %0, %1, %2, %3;" : "=l"(d) : "l"(a), "l"(b), "l"(d));
}

constexpr int MT  = 128;   // rows per CTA
constexpr int MTP = 132;   // padded smem stride for x tile
constexpr int KC  = 32;    // K chunk
constexpr int NE  = 128;   // 64 clean + 64 noise columns

union U2 { u64 u; float f[2]; };
union BU { float4 v; u64 u[2]; };

__device__ __forceinline__ float softplus_f(float z) {
    // log1p(exp(z)) stable
    return (z > 0.0f) ? (z + log1pf(expf(-z))) : log1pf(expf(z));
}

__global__ void __launch_bounds__(256, 2)
router_kernel(const float* __restrict__ x,
              const float* __restrict__ gate_w,
              const float* __restrict__ gate_b,
              const float* __restrict__ w_noise,
              const float* __restrict__ noise,
              float* __restrict__ out, int B)
{
    extern __shared__ float sm[];
    float* xs = sm;              // [KC][MTP]
    float* ws = sm + KC * MTP;   // [KC][NE]
    __shared__ float imp_s[EXP];
    __shared__ int   load_s[EXP];

    const int tid = threadIdx.x;
    const int m0  = blockIdx.x * MT;
    const int tm  = tid >> 4;    // 0..15  (row group within tile)
    const int tn  = tid & 15;    // 0..15  (expert group: experts tn*4..tn*4+3)

    if (tid < EXP) { imp_s[tid] = 0.0f; load_s[tid] = 0; }

    // accumulators: [rowgroup rg][row rr][0=clean/1=noise][col pair]
    u64 acc[2][4][2][2];
    #pragma unroll
    for (int a = 0; a < 2; a++)
        #pragma unroll
        for (int b = 0; b < 4; b++)
            #pragma unroll
            for (int c = 0; c < 2; c++) { acc[a][b][c][0] = 0ull; acc[a][b][c][1] = 0ull; }

    float4 xr[4], wr[4];

    // prefetch chunk 0
    {
        #pragma unroll
        for (int i = 0; i < 4; i++) {
            int t = tid + i * 256;
            int r = t >> 3, kq = t & 7;
            xr[i] = *(const float4*)(x + (size_t)(m0 + r) * DID + kq * 4);
        }
        #pragma unroll
        for (int i = 0; i < 4; i++) {
            int t = tid + i * 256;
            const float* src = (t < 512) ? gate_w : w_noise;
            int tt = t & 511;
            int kr = tt >> 4, c4 = tt & 15;
            wr[i] = *(const float4*)(src + (size_t)kr * EXP + c4 * 4);
        }
    }

    const int NCH = DID / KC;  // 128 chunks
    for (int kc = 0; kc < NCH; kc++) {
        __syncthreads();
        // store staged tile to smem
        #pragma unroll
        for (int i = 0; i < 4; i++) {
            int t = tid + i * 256;
            int r = t >> 3, kq = t & 7;
            float4 v = xr[i];
            xs[(kq * 4 + 0) * MTP + r] = v.x;
            xs[(kq * 4 + 1) * MTP + r] = v.y;
            xs[(kq * 4 + 2) * MTP + r] = v.z;
            xs[(kq * 4 + 3) * MTP + r] = v.w;
        }
        #pragma unroll
        for (int i = 0; i < 4; i++) {
            int t = tid + i * 256;
            int half = (t < 512) ? 0 : 64;
            int tt = t & 511;
            int kr = tt >> 4, c4 = tt & 15;
            *(float4*)(ws + kr * NE + half + c4 * 4) = wr[i];
        }
        __syncthreads();

        // prefetch next chunk (hides DRAM latency under compute)
        if (kc + 1 < NCH) {
            const int k0 = (kc + 1) * KC;
            #pragma unroll
            for (int i = 0; i < 4; i++) {
                int t = tid + i * 256;
                int r = t >> 3, kq = t & 7;
                xr[i] = *(const float4*)(x + (size_t)(m0 + r) * DID + k0 + kq * 4);
            }
            #pragma unroll
            for (int i = 0; i < 4; i++) {
                int t = tid + i * 256;
                const float* src = (t < 512) ? gate_w : w_noise;
                int tt = t & 511;
                int kr = tt >> 4, c4 = tt & 15;
                wr[i] = *(const float4*)(src + (size_t)(k0 + kr) * EXP + c4 * 4);
            }
        }

        // compute: 32 k-steps, packed f32x2 FMAs
        #pragma unroll 8
        for (int kk = 0; kk < KC; kk++) {
            float4 a0 = *(const float4*)(xs + kk * MTP + tm * 4);
            float4 a1 = *(const float4*)(xs + kk * MTP + 64 + tm * 4);
            BU b0, b1;
            b0.v = *(const float4*)(ws + kk * NE + tn * 4);
            b1.v = *(const float4*)(ws + kk * NE + 64 + tn * 4);
            float av[8] = {a0.x, a0.y, a0.z, a0.w, a1.x, a1.y, a1.z, a1.w};
            #pragma unroll
            for (int rg = 0; rg < 2; rg++) {
                #pragma unroll
                for (int rr = 0; rr < 4; rr++) {
                    u64 A = dup2f(av[rg * 4 + rr]);
                    ffma2(acc[rg][rr][0][0], A, b0.u[0]);
                    ffma2(acc[rg][rr][0][1], A, b0.u[1]);
                    ffma2(acc[rg][rr][1][0], A, b1.u[0]);
                    ffma2(acc[rg][rr][1][1], A, b1.u[1]);
                }
            }
        }
    }

    __syncthreads();

    // ---- epilogue: combine, softmax, top-2, importance/load ----
    float bias[4];
    #pragma unroll
    for (int cc = 0; cc < 4; cc++) bias[cc] = gate_b[tn * 4 + cc];

    float imp_loc[4] = {0.f, 0.f, 0.f, 0.f};
    float* out_idx = out + (size_t)B * 2;

    #pragma unroll
    for (int rg = 0; rg < 2; rg++) {
        #pragma unroll
        for (int rr = 0; rr < 4; rr++) {
            int row = m0 + rg * 64 + tm * 4 + rr;
            float4 nz4 = *(const float4*)(noise + (size_t)row * EXP + tn * 4);
            float nzv[4] = {nz4.x, nz4.y, nz4.z, nz4.w};
            float l[4];
            #pragma unroll
            for (int cc = 0; cc < 4; cc++) {
                U2 pc, pn;
                pc.u = acc[rg][rr][0][cc >> 1];
                pn.u = acc[rg][rr][1][cc >> 1];
                float cl = pc.f[cc & 1] + bias[cc];
                float nl = pn.f[cc & 1];
                l[cc] = fmaf(nzv[cc], softplus_f(nl), cl);
            }

            // top-1 (lowest index wins ties, matching jax.lax.top_k)
            float v1 = -INFINITY; int i1 = 0;
            #pragma unroll
            for (int cc = 0; cc < 4; cc++) {
                int e = tn * 4 + cc;
                if (l[cc] > v1) { v1 = l[cc]; i1 = e; }
            }
            #pragma unroll
            for (int off = 8; off; off >>= 1) {
                float ov = __shfl_xor_sync(0xffffffffu, v1, off, 16);
                int   oi = __shfl_xor_sync(0xffffffffu, i1, off, 16);
                if (ov > v1 || (ov == v1 && oi < i1)) { v1 = ov; i1 = oi; }
            }

            // row softmax (for importance)
            float ex[4];
            float esum = 0.0f;
            #pragma unroll
            for (int cc = 0; cc < 4; cc++) { ex[cc] = expf(l[cc] - v1); esum += ex[cc]; }
            #pragma unroll
            for (int off = 8; off; off >>= 1)
                esum += __shfl_xor_sync(0xffffffffu, esum, off, 16);
            float inv = 1.0f / esum;
            #pragma unroll
            for (int cc = 0; cc < 4; cc++) imp_loc[cc] += ex[cc] * inv;

            // top-2 (exclude i1)
            float v2 = -INFINITY; int i2 = 0x7fffffff;
            #pragma unroll
            for (int cc = 0; cc < 4; cc++) {
                int e = tn * 4 + cc;
                if (e != i1 && l[cc] > v2) { v2 = l[cc]; i2 = e; }
            }
            #pragma unroll
            for (int off = 8; off; off >>= 1) {
                float ov = __shfl_xor_sync(0xffffffffu, v2, off, 16);
                int   oi = __shfl_xor_sync(0xffffffffu, i2, off, 16);
                if (ov > v2 || (ov == v2 && oi < i2)) { v2 = ov; i2 = oi; }
            }

            if ((tid & 15) == 0) {
                float e21 = expf(v2 - v1);       // <= 1
                float g1 = 1.0f / (1.0f + e21);
                float g2 = e21 * g1;
                out[(size_t)row * 2 + 0] = g1;
                out[(size_t)row * 2 + 1] = g2;
                out_idx[(size_t)row * 2 + 0] = (float)i1;
                out_idx[(size_t)row * 2 + 1] = (float)i2;
                atomicAdd(&load_s[i1], 1);
                atomicAdd(&load_s[i2], 1);
            }
        }
    }

    #pragma unroll
    for (int cc = 0; cc < 4; cc++) atomicAdd(&imp_s[tn * 4 + cc], imp_loc[cc]);
    __syncthreads();
    if (tid < EXP) {
        atomicAdd(&g_importance[tid], imp_s[tid]);
        atomicAdd(&g_load[tid], load_s[tid]);
    }
}

__global__ void finalize_kernel(float* __restrict__ out, int B) {
    __shared__ float s[EXP];
    int t = threadIdx.x;
    s[t] = g_importance[t] * (float)g_load[t];
    __syncthreads();
    if (t == 0) {
        float tot = 0.0f;
        #pragma unroll
        for (int i = 0; i < EXP; i++) tot += s[i];
        // aux = mean(imp*load) * E^2 = sum * E
        out[(size_t)B * 4] = tot * (float)EXP;
    }
}

extern "C" void kernel_launch(void* const* d_in, const int* in_sizes, int n_in,
                              void* d_out, int out_size) {
    const float* x      = (const float*)d_in[0];
    const float* gate_w = (const float*)d_in[1];
    const float* gate_b = (const float*)d_in[2];
    const float* w_noise= (const float*)d_in[3];
    const float* noise  = (const float*)d_in[4];
    float* out = (float*)d_out;

    int B = in_sizes[0] / DID;

    init_kernel<<<1, EXP>>>();
    size_t smem = (size_t)(KC * MTP + KC * NE) * sizeof(float);
    router_kernel<<<B / MT, 256, smem>>>(x, gate_w, gate_b, w_noise, noise, out, B);
    finalize_kernel<<<1, EXP>>>(out, B);
}

// round 4
// speedup vs baseline: 1.7713x; 1.7713x over previous
#include <cuda_runtime.h>
#include <cuda_fp16.h>
#include <math.h>

typedef unsigned int u32;

#define DID 4096
#define EXP 64
#define NE 128          // 64 clean + 64 noise output columns
#define MT 128          // rows per CTA
#define KC 64           // k per chunk
#define NCH (DID / KC)  // 64 chunks
#define THREADS 256
#define RSCALE 4096.0f
#define INV_RSCALE (1.0f / 4096.0f)

// ---------------- global scratch ----------------
__device__ unsigned short g_w0[NE][DID];   // fp16 main limb of [clean|noise] weights, [n][k]
__device__ unsigned short g_w1[NE][DID];   // fp16 residual limb (pre-scaled by 4096)
__device__ float g_importance[EXP];
__device__ int   g_load[EXP];
__device__ int   g_count;

// ---------------- smem layout (dynamic) ----------------
// [0, 64K)        x fp32 staging, 2 stages x 32KB
// [64K, 128K)     A fp16 limb tiles: (stage,limb) x 16KB   [row 0..127][k 0..63] swizzled
// [128K, 192K)    B fp16 limb tiles: (stage,limb) x 16KB   [n 0..127][k 0..63] swizzled
// [192K, +1K)     control: bias(256B), imp(256B), load(256B), is_last(4B)
// logits overlay [128][132] f32 = 67584B reuses [0, 67584) after the mainloop.
#define XS_OFF(s)   ((s) * 32768)
#define A_OFF(s, l) (65536 + ((s) * 2 + (l)) * 16384)
#define B_OFF(s, l) (131072 + ((s) * 2 + (l)) * 16384)
#define CTRL_OFF    196608
#define SMEM_BYTES  (196608 + 1024)
#define LSTRIDE     132

// ---------------- PTX helpers ----------------
__device__ __forceinline__ u32 smem_u32(const void* p) {
    u32 a;
    asm("{ .reg .u64 t; cvta.to.shared.u64 t, %1; cvt.u32.u64 %0, t; }" : "=r"(a) : "l"(p));
    return a;
}
__device__ __forceinline__ void cp16(u32 dst, const void* src) {
    asm volatile("cp.async.cg.shared.global [%0], [%1], 16;" :: "r"(dst), "l"(src));
}
#define CP_COMMIT() asm volatile("cp.async.commit_group;")
#define CP_WAIT1()  asm volatile("cp.async.wait_group 1;")
#define CP_WAIT0()  asm volatile("cp.async.wait_group 0;")

__device__ __forceinline__ void ldsm4(u32 addr, u32& r0, u32& r1, u32& r2, u32& r3) {
    asm volatile("ldmatrix.sync.aligned.m8n8.x4.shared.b16 {%0,%1,%2,%3}, [%4];"
                 : "=r"(r0), "=r"(r1), "=r"(r2), "=r"(r3) : "r"(addr));
}
__device__ __forceinline__ void mma16816(float* d, const u32* a, const u32* b) {
    asm volatile("mma.sync.aligned.m16n8k16.row.col.f32.f16.f16.f32 "
                 "{%0,%1,%2,%3}, {%4,%5,%6,%7}, {%8,%9}, {%0,%1,%2,%3};"
                 : "+f"(d[0]), "+f"(d[1]), "+f"(d[2]), "+f"(d[3])
                 : "r"(a[0]), "r"(a[1]), "r"(a[2]), "r"(a[3]), "r"(b[0]), "r"(b[1]));
}

__device__ __forceinline__ void split2(float v, unsigned short& h0, unsigned short& h1) {
    __half a = __float2half_rn(v);
    float r = (v - __half2float(a)) * RSCALE;   // exact residual, exact scale (pow2)
    __half b = __float2half_rn(r);
    h0 = __half_as_ushort(a);
    h1 = __half_as_ushort(b);
}

__device__ __forceinline__ float softplus_f(float z) {
    return (z > 0.0f) ? (z + log1pf(expf(-z))) : log1pf(expf(z));
}

// ---------------- weight pre-split kernel ----------------
__global__ void __launch_bounds__(256) split_w_kernel(const float* __restrict__ gw,
                                                      const float* __restrict__ wn) {
    __shared__ float t[64][65];
    int k0 = blockIdx.x * 64;
    for (int half = 0; half < 2; half++) {
        const float* src = half ? wn : gw;
        __syncthreads();
        for (int i = threadIdx.x; i < 64 * 64; i += 256) {
            int kk = i >> 6, n = i & 63;
            t[n][kk] = src[(size_t)(k0 + kk) * EXP + n];
        }
        __syncthreads();
        for (int i = threadIdx.x; i < 64 * 16; i += 256) {
            int n = i >> 4, c = i & 15;          // 4 floats per item
            int nn = half * 64 + n;
            unsigned short h0[4], h1[4];
            #pragma unroll
            for (int j = 0; j < 4; j++) split2(t[n][c * 4 + j], h0[j], h1[j]);
            *(uint2*)&g_w0[nn][k0 + c * 4] =
                make_uint2((u32)h0[0] | ((u32)h0[1] << 16), (u32)h0[2] | ((u32)h0[3] << 16));
            *(uint2*)&g_w1[nn][k0 + c * 4] =
                make_uint2((u32)h1[0] | ((u32)h1[1] << 16), (u32)h1[2] | ((u32)h1[3] << 16));
        }
    }
}

// ---------------- main router kernel ----------------
__global__ void __launch_bounds__(THREADS, 1)
router_kernel(const float* __restrict__ x,
              const float* __restrict__ gate_b,
              const float* __restrict__ noise,
              float* __restrict__ out, int B, int nblocks)
{
    extern __shared__ __align__(1024) char smc[];
    const u32 sb = smem_u32(smc);
    float* bias_s  = (float*)(smc + CTRL_OFF);
    float* imp_s   = (float*)(smc + CTRL_OFF + 256);
    int*   load_s  = (int*)(smc + CTRL_OFF + 512);
    int*   is_last = (int*)(smc + CTRL_OFF + 768);

    const int tid = threadIdx.x;
    const int wid = tid >> 5, lane = tid & 31;
    const int m0 = blockIdx.x * MT;
    const int mwarp = wid & 3;        // 4 row groups of 32
    const int nwarp = wid >> 2;       // 2 col groups of 64

    if (tid < EXP) { bias_s[tid] = gate_b[tid]; imp_s[tid] = 0.0f; load_s[tid] = 0; }

    float accM[2][8][4], accC[2][8][4];
    #pragma unroll
    for (int mt = 0; mt < 2; mt++)
        #pragma unroll
        for (int nt = 0; nt < 8; nt++)
            #pragma unroll
            for (int r = 0; r < 4; r++) { accM[mt][nt][r] = 0.0f; accC[mt][nt][r] = 0.0f; }

    // ldmatrix lane constants
    const int a_row = lane & 15;
    const int a_kb  = lane >> 4;                         // 0/1 -> k+8
    const int b_row = (lane & 7) + ((lane >> 4) & 1) * 8;
    const int b_kb  = (lane >> 3) & 1;

    // ---- prologue: issue chunk 0 into stage 0 ----
    {
        #pragma unroll
        for (int i = 0; i < 8; i++) {
            int u = tid + i * 256;
            int row = u >> 4, cu = u & 15;
            cp16(sb + XS_OFF(0) + u * 16, x + (size_t)(m0 + row) * DID + cu * 4);
        }
        #pragma unroll
        for (int i = 0; i < 4; i++) {
            int u = tid + i * 256;
            int n = u >> 3, cu = u & 7;
            u32 sw = (u32)(n * 128 + ((cu ^ (n & 7)) * 16));
            cp16(sb + B_OFF(0, 0) + sw, &g_w0[n][cu * 8]);
            cp16(sb + B_OFF(0, 1) + sw, &g_w1[n][cu * 8]);
        }
        CP_COMMIT();
    }

    for (int kc = 0; kc < NCH; kc++) {
        const int s = kc & 1;
        __syncthreads();   // all warps done with mma(kc-1): safe to refill stage s^1

        if (kc + 1 < NCH) {
            const int k0n = (kc + 1) * KC;
            #pragma unroll
            for (int i = 0; i < 8; i++) {
                int u = tid + i * 256;
                int row = u >> 4, cu = u & 15;
                cp16(sb + XS_OFF(s ^ 1) + u * 16, x + (size_t)(m0 + row) * DID + k0n + cu * 4);
            }
            #pragma unroll
            for (int i = 0; i < 4; i++) {
                int u = tid + i * 256;
                int n = u >> 3, cu = u & 7;
                u32 sw = (u32)(n * 128 + ((cu ^ (n & 7)) * 16));
                cp16(sb + B_OFF(s ^ 1, 0) + sw, &g_w0[n][k0n + cu * 8]);
                cp16(sb + B_OFF(s ^ 1, 1) + sw, &g_w1[n][k0n + cu * 8]);
            }
            CP_COMMIT();
            CP_WAIT1();   // chunk kc arrived
        } else {
            CP_WAIT0();
        }

        // convert x fp32 -> 2 fp16 limbs (swizzled A tiles) — ALL 128 rows (8 iters)
        #pragma unroll
        for (int i = 0; i < 8; i++) {
            int u = tid + i * 256;
            int row = u >> 4, c = u & 15;
            float4 v = *(const float4*)(smc + XS_OFF(s) + u * 16);
            unsigned short h0[4], h1[4];
            split2(v.x, h0[0], h1[0]);
            split2(v.y, h0[1], h1[1]);
            split2(v.z, h0[2], h1[2]);
            split2(v.w, h0[3], h1[3]);
            u32 off = (u32)(row * 128 + (((c >> 1) ^ (row & 7)) * 16) + (c & 1) * 8);
            *(uint2*)(smc + A_OFF(s, 0) + off) =
                make_uint2((u32)h0[0] | ((u32)h0[1] << 16), (u32)h0[2] | ((u32)h0[3] << 16));
            *(uint2*)(smc + A_OFF(s, 1) + off) =
                make_uint2((u32)h1[0] | ((u32)h1[1] << 16), (u32)h1[2] | ((u32)h1[3] << 16));
        }
        __syncthreads();

        // ---- mma over this chunk: 4 k-steps of 16 ----
        const u32 ab0 = sb + A_OFF(s, 0), ab1 = sb + A_OFF(s, 1);
        const u32 bb0 = sb + B_OFF(s, 0), bb1 = sb + B_OFF(s, 1);
        #pragma unroll
        for (int ks = 0; ks < 4; ks++) {
            u32 A0[2][4], A1[2][4];
            #pragma unroll
            for (int mt = 0; mt < 2; mt++) {
                int row = mwarp * 32 + mt * 16 + a_row;
                u32 off = (u32)(row * 128 + (((ks * 2 + a_kb) ^ (row & 7)) * 16));
                ldsm4(ab0 + off, A0[mt][0], A0[mt][1], A0[mt][2], A0[mt][3]);
                ldsm4(ab1 + off, A1[mt][0], A1[mt][1], A1[mt][2], A1[mt][3]);
            }
            u32 B0[8][2], B1[8][2];
            #pragma unroll
            for (int p = 0; p < 4; p++) {
                int n = nwarp * 64 + p * 16 + b_row;
                u32 off = (u32)(n * 128 + (((ks * 2 + b_kb) ^ (n & 7)) * 16));
                u32 r0, r1, r2, r3;
                ldsm4(bb0 + off, r0, r1, r2, r3);
                B0[p * 2][0] = r0; B0[p * 2][1] = r1; B0[p * 2 + 1][0] = r2; B0[p * 2 + 1][1] = r3;
                ldsm4(bb1 + off, r0, r1, r2, r3);
                B1[p * 2][0] = r0; B1[p * 2][1] = r1; B1[p * 2 + 1][0] = r2; B1[p * 2 + 1][1] = r3;
            }
            #pragma unroll
            for (int mt = 0; mt < 2; mt++)
                #pragma unroll
                for (int nt = 0; nt < 8; nt++) {
                    mma16816(accM[mt][nt], A0[mt], B0[nt]);
                    mma16816(accC[mt][nt], A0[mt], B1[nt]);
                    mma16816(accC[mt][nt], A1[mt], B0[nt]);
                }
        }
    }

    __syncthreads();

    // ---- write combined logits to smem overlay [128][LSTRIDE] ----
    float* lsm = (float*)smc;
    {
        const int gid = lane >> 2, tig = lane & 3;
        #pragma unroll
        for (int mt = 0; mt < 2; mt++)
            #pragma unroll
            for (int nt = 0; nt < 8; nt++) {
                int r0 = mwarp * 32 + mt * 16 + gid;
                int cc = nwarp * 64 + nt * 8 + tig * 2;
                float f0 = accM[mt][nt][0] + accC[mt][nt][0] * INV_RSCALE;
                float f1 = accM[mt][nt][1] + accC[mt][nt][1] * INV_RSCALE;
                float f2 = accM[mt][nt][2] + accC[mt][nt][2] * INV_RSCALE;
                float f3 = accM[mt][nt][3] + accC[mt][nt][3] * INV_RSCALE;
                *(float2*)&lsm[r0 * LSTRIDE + cc]       = make_float2(f0, f1);
                *(float2*)&lsm[(r0 + 8) * LSTRIDE + cc] = make_float2(f2, f3);
            }
    }
    __syncthreads();

    // ---- epilogue: warps 0-3, one row per lane ----
    if (wid < 4) {
        const int rloc = wid * 32 + lane;
        const int row = m0 + rloc;
        const float* nrow = noise + (size_t)row * EXP;
        float l[64];
        #pragma unroll
        for (int e = 0; e < 64; e += 4) {
            float4 cl = *(const float4*)&lsm[rloc * LSTRIDE + e];
            float4 nl = *(const float4*)&lsm[rloc * LSTRIDE + 64 + e];
            float4 nz = *(const float4*)(nrow + e);
            l[e + 0] = fmaf(nz.x, softplus_f(nl.x), cl.x + bias_s[e + 0]);
            l[e + 1] = fmaf(nz.y, softplus_f(nl.y), cl.y + bias_s[e + 1]);
            l[e + 2] = fmaf(nz.z, softplus_f(nl.z), cl.z + bias_s[e + 2]);
            l[e + 3] = fmaf(nz.w, softplus_f(nl.w), cl.w + bias_s[e + 3]);
        }

        // top-2, lowest index wins ties (matches jax.lax.top_k)
        float v1 = -INFINITY, v2 = -INFINITY;
        int i1 = -1, i2 = -1;
        #pragma unroll
        for (int e = 0; e < 64; e++) {
            float le = l[e];
            if (le > v1) { v2 = v1; i2 = i1; v1 = le; i1 = e; }
            else if (le > v2) { v2 = le; i2 = e; }
        }

        // full softmax for importance
        float esum = 0.0f;
        #pragma unroll
        for (int e = 0; e < 64; e++) { l[e] = expf(l[e] - v1); esum += l[e]; }
        float inv = 1.0f / esum;

        #pragma unroll
        for (int e = 0; e < 64; e++) {
            float p = l[e] * inv;
            p += __shfl_xor_sync(0xffffffffu, p, 16);
            p += __shfl_xor_sync(0xffffffffu, p, 8);
            p += __shfl_xor_sync(0xffffffffu, p, 4);
            p += __shfl_xor_sync(0xffffffffu, p, 2);
            p += __shfl_xor_sync(0xffffffffu, p, 1);
            if (lane == 0) atomicAdd(&imp_s[e], p);
        }

        float e21 = expf(v2 - v1);
        float g1 = 1.0f / (1.0f + e21);
        float g2 = e21 * g1;
        *(float2*)(out + (size_t)row * 2) = make_float2(g1, g2);
        *(float2*)(out + (size_t)B * 2 + (size_t)row * 2) = make_float2((float)i1, (float)i2);
        atomicAdd(&load_s[i1], 1);
        atomicAdd(&load_s[i2], 1);
    }
    __syncthreads();

    if (tid < EXP) {
        atomicAdd(&g_importance[tid], imp_s[tid]);
        atomicAdd(&g_load[tid], load_s[tid]);
    }

    // last CTA: finalize aux loss + reset globals for the next graph replay
    __threadfence();
    if (tid == 0) {
        int c = atomicAdd(&g_count, 1);
        *is_last = (c == nblocks - 1) ? 1 : 0;
    }
    __syncthreads();
    if (*is_last) {
        if (tid < EXP) imp_s[tid] = g_importance[tid] * (float)g_load[tid];
        __syncthreads();
        if (tid == 0) {
            float tot = 0.0f;
            #pragma unroll
            for (int i = 0; i < EXP; i++) tot += imp_s[i];
            out[(size_t)B * 4] = tot * (float)EXP;   // mean * E^2 = sum * E
            g_count = 0;
        }
        if (tid < EXP) { g_importance[tid] = 0.0f; g_load[tid] = 0; }
    }
}

extern "C" void kernel_launch(void* const* d_in, const int* in_sizes, int n_in,
                              void* d_out, int out_size) {
    const float* x       = (const float*)d_in[0];
    const float* gate_w  = (const float*)d_in[1];
    const float* gate_b  = (const float*)d_in[2];
    const float* w_noise = (const float*)d_in[3];
    const float* noise   = (const float*)d_in[4];
    float* out = (float*)d_out;

    int B = in_sizes[0] / DID;
    int nblocks = B / MT;

    cudaFuncSetAttribute(router_kernel, cudaFuncAttributeMaxDynamicSharedMemorySize, SMEM_BYTES);

    split_w_kernel<<<DID / 64, 256>>>(gate_w, w_noise);
    router_kernel<<<nblocks, THREADS, SMEM_BYTES>>>(x, gate_b, noise, out, B, nblocks);
}

// round 5
// speedup vs baseline: 1.9327x; 1.0911x over previous
#include <cuda_runtime.h>
#include <cuda_fp16.h>
#include <math.h>

typedef unsigned int u32;

#define DID 4096
#define EXP 64
#define NE 128          // 64 clean + 64 noise output columns
#define MT 128          // rows per CTA
#define KC 64           // k per chunk
#define NCH (DID / KC)  // 64 chunks
#define THREADS 512
#define RSCALE 4096.0f
#define INV_RSCALE (1.0f / 4096.0f)

// ---------------- global scratch ----------------
__device__ unsigned short g_w0[NE][DID];   // fp16 main limb of [clean|noise] weights, [n][k]
__device__ unsigned short g_w1[NE][DID];   // fp16 residual limb (pre-scaled by 4096)
__device__ float g_importance[EXP];
__device__ int   g_load[EXP];
__device__ int   g_count;

// ---------------- smem layout (dynamic) ----------------
// [0, 64K)        x fp32 staging, 2 stages x 32KB
// [64K, 96K)      A fp16 limb tiles (single stage): limb x 16KB
// [96K, 160K)     B fp16 limb tiles: (stage,limb) x 16KB
// [160K, +1K)     control
// logits overlay [128][132] f32 = 67584B reuses [0, 67584) after the mainloop.
#define XS_OFF(s)   ((s) * 32768)
#define A_OFF(l)    (65536 + (l) * 16384)
#define B_OFF(s, l) (98304 + ((s) * 2 + (l)) * 16384)
#define CTRL_OFF    163840
#define SMEM_BYTES  (163840 + 1024)
#define LSTRIDE     132

// ---------------- PTX helpers ----------------
__device__ __forceinline__ u32 smem_u32(const void* p) {
    u32 a;
    asm("{ .reg .u64 t; cvta.to.shared.u64 t, %1; cvt.u32.u64 %0, t; }" : "=r"(a) : "l"(p));
    return a;
}
__device__ __forceinline__ void cp16(u32 dst, const void* src) {
    asm volatile("cp.async.cg.shared.global [%0], [%1], 16;" :: "r"(dst), "l"(src));
}
#define CP_COMMIT() asm volatile("cp.async.commit_group;")
#define CP_WAIT1()  asm volatile("cp.async.wait_group 1;")
#define CP_WAIT0()  asm volatile("cp.async.wait_group 0;")

__device__ __forceinline__ void ldsm4(u32 addr, u32& r0, u32& r1, u32& r2, u32& r3) {
    asm volatile("ldmatrix.sync.aligned.m8n8.x4.shared.b16 {%0,%1,%2,%3}, [%4];"
                 : "=r"(r0), "=r"(r1), "=r"(r2), "=r"(r3) : "r"(addr));
}
// fp32-accumulate HMMA (main term)
__device__ __forceinline__ void mma_f32(float* d, const u32* a, const u32* b) {
    asm volatile("mma.sync.aligned.m16n8k16.row.col.f32.f16.f16.f32 "
                 "{%0,%1,%2,%3}, {%4,%5,%6,%7}, {%8,%9}, {%0,%1,%2,%3};"
                 : "+f"(d[0]), "+f"(d[1]), "+f"(d[2]), "+f"(d[3])
                 : "r"(a[0]), "r"(a[1]), "r"(a[2]), "r"(a[3]), "r"(b[0]), "r"(b[1]));
}
// fp16-accumulate HMMA (cross terms; values ~|15| max, rounding folded by /4096)
__device__ __forceinline__ void mma_f16(u32* d, const u32* a, const u32* b) {
    asm volatile("mma.sync.aligned.m16n8k16.row.col.f16.f16.f16.f16 "
                 "{%0,%1}, {%2,%3,%4,%5}, {%6,%7}, {%0,%1};"
                 : "+r"(d[0]), "+r"(d[1])
                 : "r"(a[0]), "r"(a[1]), "r"(a[2]), "r"(a[3]), "r"(b[0]), "r"(b[1]));
}

__device__ __forceinline__ void split2(float v, unsigned short& h0, unsigned short& h1) {
    __half a = __float2half_rn(v);
    float r = (v - __half2float(a)) * RSCALE;   // exact residual, exact pow2 scale
    __half b = __float2half_rn(r);
    h0 = __half_as_ushort(a);
    h1 = __half_as_ushort(b);
}

__device__ __forceinline__ float softplus_f(float z) {
    return (z > 0.0f) ? (z + log1pf(expf(-z))) : log1pf(expf(z));
}

// ---------------- weight pre-split kernel ----------------
__global__ void __launch_bounds__(256) split_w_kernel(const float* __restrict__ gw,
                                                      const float* __restrict__ wn) {
    __shared__ float t[64][65];
    int k0 = blockIdx.x * 64;
    for (int half = 0; half < 2; half++) {
        const float* src = half ? wn : gw;
        __syncthreads();
        for (int i = threadIdx.x; i < 64 * 64; i += 256) {
            int kk = i >> 6, n = i & 63;
            t[n][kk] = src[(size_t)(k0 + kk) * EXP + n];
        }
        __syncthreads();
        for (int i = threadIdx.x; i < 64 * 16; i += 256) {
            int n = i >> 4, c = i & 15;
            int nn = half * 64 + n;
            unsigned short h0[4], h1[4];
            #pragma unroll
            for (int j = 0; j < 4; j++) split2(t[n][c * 4 + j], h0[j], h1[j]);
            *(uint2*)&g_w0[nn][k0 + c * 4] =
                make_uint2((u32)h0[0] | ((u32)h0[1] << 16), (u32)h0[2] | ((u32)h0[3] << 16));
            *(uint2*)&g_w1[nn][k0 + c * 4] =
                make_uint2((u32)h1[0] | ((u32)h1[1] << 16), (u32)h1[2] | ((u32)h1[3] << 16));
        }
    }
}

// ---------------- main router kernel ----------------
__global__ void __launch_bounds__(THREADS, 1)
router_kernel(const float* __restrict__ x,
              const float* __restrict__ gate_b,
              const float* __restrict__ noise,
              float* __restrict__ out, int B, int nblocks)
{
    extern __shared__ __align__(1024) char smc[];
    const u32 sb = smem_u32(smc);
    float* bias_s  = (float*)(smc + CTRL_OFF);
    float* imp_s   = (float*)(smc + CTRL_OFF + 256);
    int*   load_s  = (int*)(smc + CTRL_OFF + 512);
    int*   is_last = (int*)(smc + CTRL_OFF + 768);

    const int tid = threadIdx.x;
    const int wid = tid >> 5, lane = tid & 31;
    const int m0 = blockIdx.x * MT;
    const int mwarp = wid & 3;        // 4 row groups of 32
    const int nwarp = wid >> 2;       // 4 col groups of 32

    if (tid < EXP) { bias_s[tid] = gate_b[tid]; imp_s[tid] = 0.0f; load_s[tid] = 0; }

    float accM[2][4][4];   // fp32 main accumulator, 32 regs
    u32   accC[2][4][2];   // fp16x2 cross accumulator, 16 regs
    #pragma unroll
    for (int mt = 0; mt < 2; mt++)
        #pragma unroll
        for (int nt = 0; nt < 4; nt++) {
            #pragma unroll
            for (int r = 0; r < 4; r++) accM[mt][nt][r] = 0.0f;
            accC[mt][nt][0] = 0u; accC[mt][nt][1] = 0u;
        }

    // ldmatrix lane constants
    const int a_row = lane & 15;
    const int a_kb  = lane >> 4;
    const int b_row = (lane & 7) + ((lane >> 4) & 1) * 8;
    const int b_kb  = (lane >> 3) & 1;

    // ---- prologue: issue chunk 0 into stage 0 ----
    {
        #pragma unroll
        for (int i = 0; i < 4; i++) {
            int u = tid + i * 512;
            int row = u >> 4, cu = u & 15;
            cp16(sb + XS_OFF(0) + u * 16, x + (size_t)(m0 + row) * DID + cu * 4);
        }
        #pragma unroll
        for (int i = 0; i < 2; i++) {
            int u = tid + i * 512;
            int n = u >> 3, cu = u & 7;
            u32 sw = (u32)(n * 128 + ((cu ^ (n & 7)) * 16));
            cp16(sb + B_OFF(0, 0) + sw, &g_w0[n][cu * 8]);
            cp16(sb + B_OFF(0, 1) + sw, &g_w1[n][cu * 8]);
        }
        CP_COMMIT();
    }

    for (int kc = 0; kc < NCH; kc++) {
        const int s = kc & 1;
        __syncthreads();   // all warps done with mma(kc-1): A tile free, stage s^1 free

        if (kc + 1 < NCH) {
            const int k0n = (kc + 1) * KC;
            #pragma unroll
            for (int i = 0; i < 4; i++) {
                int u = tid + i * 512;
                int row = u >> 4, cu = u & 15;
                cp16(sb + XS_OFF(s ^ 1) + u * 16, x + (size_t)(m0 + row) * DID + k0n + cu * 4);
            }
            #pragma unroll
            for (int i = 0; i < 2; i++) {
                int u = tid + i * 512;
                int n = u >> 3, cu = u & 7;
                u32 sw = (u32)(n * 128 + ((cu ^ (n & 7)) * 16));
                cp16(sb + B_OFF(s ^ 1, 0) + sw, &g_w0[n][k0n + cu * 8]);
                cp16(sb + B_OFF(s ^ 1, 1) + sw, &g_w1[n][k0n + cu * 8]);
            }
            CP_COMMIT();
            CP_WAIT1();   // chunk kc arrived
        } else {
            CP_WAIT0();
        }

        // convert x fp32 -> 2 fp16 limbs into single-stage A tiles
        #pragma unroll
        for (int i = 0; i < 4; i++) {
            int u = tid + i * 512;
            int row = u >> 4, c = u & 15;
            float4 v = *(const float4*)(smc + XS_OFF(s) + u * 16);
            unsigned short h0[4], h1[4];
            split2(v.x, h0[0], h1[0]);
            split2(v.y, h0[1], h1[1]);
            split2(v.z, h0[2], h1[2]);
            split2(v.w, h0[3], h1[3]);
            u32 off = (u32)(row * 128 + (((c >> 1) ^ (row & 7)) * 16) + (c & 1) * 8);
            *(uint2*)(smc + A_OFF(0) + off) =
                make_uint2((u32)h0[0] | ((u32)h0[1] << 16), (u32)h0[2] | ((u32)h0[3] << 16));
            *(uint2*)(smc + A_OFF(1) + off) =
                make_uint2((u32)h1[0] | ((u32)h1[1] << 16), (u32)h1[2] | ((u32)h1[3] << 16));
        }
        __syncthreads();

        // ---- mma over this chunk: 4 k-steps of 16 ----
        const u32 ab0 = sb + A_OFF(0), ab1 = sb + A_OFF(1);
        const u32 bb0 = sb + B_OFF(s, 0), bb1 = sb + B_OFF(s, 1);
        #pragma unroll
        for (int ks = 0; ks < 4; ks++) {
            u32 A0[2][4], A1[2][4];
            #pragma unroll
            for (int mt = 0; mt < 2; mt++) {
                int row = mwarp * 32 + mt * 16 + a_row;
                u32 off = (u32)(row * 128 + (((ks * 2 + a_kb) ^ (row & 7)) * 16));
                ldsm4(ab0 + off, A0[mt][0], A0[mt][1], A0[mt][2], A0[mt][3]);
                ldsm4(ab1 + off, A1[mt][0], A1[mt][1], A1[mt][2], A1[mt][3]);
            }
            u32 B0[4][2], B1[4][2];
            #pragma unroll
            for (int p = 0; p < 2; p++) {
                int n = nwarp * 32 + p * 16 + b_row;
                u32 off = (u32)(n * 128 + (((ks * 2 + b_kb) ^ (n & 7)) * 16));
                u32 r0, r1, r2, r3;
                ldsm4(bb0 + off, r0, r1, r2, r3);
                B0[p * 2][0] = r0; B0[p * 2][1] = r1; B0[p * 2 + 1][0] = r2; B0[p * 2 + 1][1] = r3;
                ldsm4(bb1 + off, r0, r1, r2, r3);
                B1[p * 2][0] = r0; B1[p * 2][1] = r1; B1[p * 2 + 1][0] = r2; B1[p * 2 + 1][1] = r3;
            }
            #pragma unroll
            for (int mt = 0; mt < 2; mt++)
                #pragma unroll
                for (int nt = 0; nt < 4; nt++) {
                    mma_f32(accM[mt][nt], A0[mt], B0[nt]);
                    mma_f16(accC[mt][nt], A0[mt], B1[nt]);
                    mma_f16(accC[mt][nt], A1[mt], B0[nt]);
                }
        }
    }

    __syncthreads();

    // ---- write combined logits to smem overlay [128][LSTRIDE] ----
    float* lsm = (float*)smc;
    {
        const int gid = lane >> 2, tig = lane & 3;
        #pragma unroll
        for (int mt = 0; mt < 2; mt++)
            #pragma unroll
            for (int nt = 0; nt < 4; nt++) {
                int r0 = mwarp * 32 + mt * 16 + gid;
                int cc = nwarp * 32 + nt * 8 + tig * 2;
                float2 c0 = __half22float2(*(__half2*)&accC[mt][nt][0]);
                float2 c1 = __half22float2(*(__half2*)&accC[mt][nt][1]);
                float f0 = fmaf(c0.x, INV_RSCALE, accM[mt][nt][0]);
                float f1 = fmaf(c0.y, INV_RSCALE, accM[mt][nt][1]);
                float f2 = fmaf(c1.x, INV_RSCALE, accM[mt][nt][2]);
                float f3 = fmaf(c1.y, INV_RSCALE, accM[mt][nt][3]);
                *(float2*)&lsm[r0 * LSTRIDE + cc]       = make_float2(f0, f1);
                *(float2*)&lsm[(r0 + 8) * LSTRIDE + cc] = make_float2(f2, f3);
            }
    }
    __syncthreads();

    // ---- epilogue: warps 0-3, one row per lane ----
    if (wid < 4) {
        const int rloc = wid * 32 + lane;
        const int row = m0 + rloc;
        const float* nrow = noise + (size_t)row * EXP;
        float l[64];
        #pragma unroll
        for (int e = 0; e < 64; e += 4) {
            float4 cl = *(const float4*)&lsm[rloc * LSTRIDE + e];
            float4 nl = *(const float4*)&lsm[rloc * LSTRIDE + 64 + e];
            float4 nz = *(const float4*)(nrow + e);
            l[e + 0] = fmaf(nz.x, softplus_f(nl.x), cl.x + bias_s[e + 0]);
            l[e + 1] = fmaf(nz.y, softplus_f(nl.y), cl.y + bias_s[e + 1]);
            l[e + 2] = fmaf(nz.z, softplus_f(nl.z), cl.z + bias_s[e + 2]);
            l[e + 3] = fmaf(nz.w, softplus_f(nl.w), cl.w + bias_s[e + 3]);
        }

        // top-2, lowest index wins ties (matches jax.lax.top_k)
        float v1 = -INFINITY, v2 = -INFINITY;
        int i1 = -1, i2 = -1;
        #pragma unroll
        for (int e = 0; e < 64; e++) {
            float le = l[e];
            if (le > v1) { v2 = v1; i2 = i1; v1 = le; i1 = e; }
            else if (le > v2) { v2 = le; i2 = e; }
        }

        // full softmax for importance
        float esum = 0.0f;
        #pragma unroll
        for (int e = 0; e < 64; e++) { l[e] = expf(l[e] - v1); esum += l[e]; }
        float inv = 1.0f / esum;

        #pragma unroll
        for (int e = 0; e < 64; e++) {
            float p = l[e] * inv;
            p += __shfl_xor_sync(0xffffffffu, p, 16);
            p += __shfl_xor_sync(0xffffffffu, p, 8);
            p += __shfl_xor_sync(0xffffffffu, p, 4);
            p += __shfl_xor_sync(0xffffffffu, p, 2);
            p += __shfl_xor_sync(0xffffffffu, p, 1);
            if (lane == 0) atomicAdd(&imp_s[e], p);
        }

        float e21 = expf(v2 - v1);
        float g1 = 1.0f / (1.0f + e21);
        float g2 = e21 * g1;
        *(float2*)(out + (size_t)row * 2) = make_float2(g1, g2);
        *(float2*)(out + (size_t)B * 2 + (size_t)row * 2) = make_float2((float)i1, (float)i2);
        atomicAdd(&load_s[i1], 1);
        atomicAdd(&load_s[i2], 1);
    }
    __syncthreads();

    if (tid < EXP) {
        atomicAdd(&g_importance[tid], imp_s[tid]);
        atomicAdd(&g_load[tid], load_s[tid]);
    }

    // last CTA: finalize aux loss + reset globals for the next graph replay
    __threadfence();
    if (tid == 0) {
        int c = atomicAdd(&g_count, 1);
        *is_last = (c == nblocks - 1) ? 1 : 0;
    }
    __syncthreads();
    if (*is_last) {
        if (tid < EXP) imp_s[tid] = g_importance[tid] * (float)g_load[tid];
        __syncthreads();
        if (tid == 0) {
            float tot = 0.0f;
            #pragma unroll
            for (int i = 0; i < EXP; i++) tot += imp_s[i];
            out[(size_t)B * 4] = tot * (float)EXP;   // mean * E^2 = sum * E
            g_count = 0;
        }
        if (tid < EXP) { g_importance[tid] = 0.0f; g_load[tid] = 0; }
    }
}

extern "C" void kernel_launch(void* const* d_in, const int* in_sizes, int n_in,
                              void* d_out, int out_size) {
    const float* x       = (const float*)d_in[0];
    const float* gate_w  = (const float*)d_in[1];
    const float* gate_b  = (const float*)d_in[2];
    const float* w_noise = (const float*)d_in[3];
    const float* noise   = (const float*)d_in[4];
    float* out = (float*)d_out;

    int B = in_sizes[0] / DID;
    int nblocks = B / MT;

    cudaFuncSetAttribute(router_kernel, cudaFuncAttributeMaxDynamicSharedMemorySize, SMEM_BYTES);

    split_w_kernel<<<DID / 64, 256>>>(gate_w, w_noise);
    router_kernel<<<nblocks, THREADS, SMEM_BYTES>>>(x, gate_b, noise, out, B, nblocks);
}